// round 14
// baseline (speedup 1.0000x reference)
#include <cuda_runtime.h>
#include <cuda_bf16.h>
#include <math.h>
#include <stdint.h>

// Problem constants
#define T_DIM   36
#define NPOLES  40
#define KDIM    160
#define PDIM    4096
#define PCOLS   64           // p columns per CTA
#define NCTA    128
#define NTHREADS 256         // 8 warps; each warp owns 8 columns end-to-end
#define MAXIT   100
#define LAM_C   0.1f
#define TOL_C   1e-4f

#define PSTR    12           // packed-pair row stride (uint2 units); 12*i4+g mod 16 uniform 2-way

// ---- dynamic smem layout (bytes) ----
#define RED_OFF   0                     // red2[4][8] floats = 128
#define WCNT_OFF  128                   // int[4]
#define DECV_OFF  144                   // int[4]
#define DECI_OFF  160                   // int[4]
#define TTS_OFF   192                   // 100 floats
#define A1H_OFF   1024                  // D48 frags (k-permuted): 30*512 = 15360
#define A1L_OFF   (A1H_OFF + 15360)
#define A2H_OFF   (A1L_OFF + 15360)     // -linv*D^T frags (k-permuted)
#define A2L_OFF   (A2H_OFF + 15360)
#define DTY_OFF   (A2L_OFF + 15360)     // 80 c-frags * 512 = 40960
#define YBUF_OFF  (DTY_OFF + 40960)     // 8 warps * 80 pairs * 12 * 8B = 61440
#define ZBUF_OFF  (YBUF_OFF + 61440)    // 8 warps * 24 pairs * 12 * 8B = 18432
#define SMEM_TOTAL (ZBUF_OFF + 18432)   // 183296
#define YBUF_WARP 7680
#define ZBUF_WARP 2304
// startup staging (inside YBUF region, consumed before zeroing):
#define DICT_STAGE YBUF_OFF             // dict [36][160] fp32 = 23040
#define X_STAGE   (YBUF_OFF + 23040)    // x tile [36][64] fp32 = 9216

// ---------------- device globals ----------------
__device__ float    g_Dmat[T_DIM * KDIM];
__device__ float    g_lambd;
__device__ float    g_linv;
__device__ float    g_tts[MAXIT];
__device__ float    g_part[4 * NCTA];   // 4-deep ring by iteration
__device__ unsigned g_count;
__device__ unsigned g_gen;              // # globally completed iterations

// ---------------- helpers ----------------
__device__ __forceinline__ void mma_bf16(float* c, const uint32_t* a, const uint32_t* b) {
    asm volatile(
        "mma.sync.aligned.m16n8k16.row.col.f32.bf16.bf16.f32 "
        "{%0,%1,%2,%3}, {%4,%5,%6,%7}, {%8,%9}, {%0,%1,%2,%3};"
        : "+f"(c[0]), "+f"(c[1]), "+f"(c[2]), "+f"(c[3])
        : "r"(a[0]), "r"(a[1]), "r"(a[2]), "r"(a[3]), "r"(b[0]), "r"(b[1]));
}
__device__ __forceinline__ void split_pack(float v0, float v1, uint32_t& hi, uint32_t& lo) {
    asm("cvt.rn.bf16x2.f32 %0, %1, %2;" : "=r"(hi) : "f"(v1), "f"(v0));
    float h0 = __uint_as_float(hi << 16);
    float h1 = __uint_as_float(hi & 0xffff0000u);
    asm("cvt.rn.bf16x2.f32 %0, %1, %2;" : "=r"(lo) : "f"(v1 - h1), "f"(v0 - h0));
}
__device__ __forceinline__ float warp_sum(float v) {
    v += __shfl_xor_sync(0xFFFFFFFFu, v, 16);
    v += __shfl_xor_sync(0xFFFFFFFFu, v, 8);
    v += __shfl_xor_sync(0xFFFFFFFFu, v, 4);
    v += __shfl_xor_sync(0xFFFFFFFFu, v, 2);
    v += __shfl_xor_sync(0xFFFFFFFFu, v, 1);
    return v;
}

// ---------------- setup ----------------
__global__ void setup_kernel(const float* __restrict__ Drr,
                             const float* __restrict__ Dtheta) {
    __shared__ float rbuf[32];
    const int tid = threadIdx.x;

    if (tid < KDIM) {
        const int j = tid;
        const int gg = j / NPOLES;
        const int n = j % NPOLES;
        const float rr = Drr[n];
        const float th = Dtheta[n];
        float vals[T_DIM];
        float pr = 1.0f, n2 = 0.0f;
        for (int i = 0; i < T_DIM; ++i) {
            float ang  = (float)i * th;
            float base = (gg < 2) ? cosf(ang) : sinf(ang);
            float v = pr * base;
            if ((gg & 1) && (i & 1)) v = -v;
            vals[i] = v; n2 += v * v; pr *= rr;
        }
        float G  = (n2 == 0.0f) ? 6.0f : sqrtf(n2);
        float gi = 1.0f / G;
        for (int i = 0; i < T_DIM; ++i) g_Dmat[i * KDIM + j] = vals[i] * gi;
    }
    __syncthreads();

    float sq = 0.0f;
    for (int e = tid; e < KDIM * KDIM; e += 1024) {
        int i = e / KDIM, jj = e % KDIM;
        float s = 0.0f;
        for (int t = 0; t < T_DIM; ++t)
            s += g_Dmat[t * KDIM + i] * g_Dmat[t * KDIM + jj];
        sq += s * s;
    }
    float ws = warp_sum(sq);
    if ((tid & 31) == 0) rbuf[tid >> 5] = ws;
    __syncthreads();
    if (tid == 0) {
        float tot = 0.0f;
        for (int i = 0; i < 32; ++i) tot += rbuf[i];
        float L = sqrtf(tot);
        float linv = 1.0f / L;
        g_linv  = linv;
        g_lambd = LAM_C * linv;
        double t = 1.0;
        for (int k = 0; k < MAXIT; ++k) {
            double tn = (1.0 + sqrt(1.0 + 4.0 * t * t)) * 0.5;
            g_tts[k] = (float)((t - 1.0) / tn);
            t = tn;
        }
        g_count = 0;
        g_gen   = 0;
    }
    if (tid < 4 * NCTA) g_part[tid] = 0.0f;
}

// ---------------- persistent FISTA kernel: warp-autonomous loop ------------
// Warp = 8-col stripe. Per iter (all warp-local, NO block syncs):
//   stage1: z[48x8] = D48 @ y        (y packed bf16 pairs, k-permuted)
//   stage2: acc[160x8] = DtY - linv*D^T @ z   (z packed pairs)
//   epilogue: v = acc + yreg; shrink; momentum; pack y pairs
// Convergence: lock-free 4-deep ring protocol, warp0 = CTA agent.
__global__ void __launch_bounds__(NTHREADS, 1)
fista_kernel(const float* __restrict__ x_in, float* __restrict__ out) {
    extern __shared__ __align__(16) char smem[];
    float* red2  = (float*)(smem + RED_OFF);
    int*   wcnt  = (int*)(smem + WCNT_OFF);
    int*   decv  = (int*)(smem + DECV_OFF);
    int*   deci  = (int*)(smem + DECI_OFF);
    float* tts_s = (float*)(smem + TTS_OFF);

    const int tid = threadIdx.x;
    const int wid = tid >> 5;
    const int l   = tid & 31;
    const int g   = l >> 2;            // 0..7
    const int i4  = l & 3;             // 0..3
    const int cta = blockIdx.x;
    const int b   = cta >> 6;
    const int p0  = (cta & 63) * PCOLS;

    const float linv  = g_linv;
    const float lambd = g_lambd;

    // ---- init control + stage dict/x; copy tts ----
    if (tid < 4) { wcnt[tid] = 0; decv[tid] = 0; deci[tid] = -1; }
    for (int e = tid; e < T_DIM * KDIM; e += NTHREADS)
        *(float*)(smem + DICT_STAGE + e * 4) = g_Dmat[e];
    for (int e = tid; e < T_DIM * PCOLS; e += NTHREADS) {
        int t = e >> 6, pp = e & 63;
        *(float*)(smem + X_STAGE + e * 4) = x_in[(b * T_DIM + t) * PDIM + p0 + pp];
    }
    if (tid < MAXIT) tts_s[tid] = g_tts[tid];
    __syncthreads();

    // ---- DtY = linv * D^T x -> c-frag regs (warp cols = wid*8..+8) ----
    {
        float dty[40];
        #pragma unroll
        for (int v = 0; v < 40; ++v) dty[v] = 0.0f;
        const float* Ds = (const float*)(smem + DICT_STAGE);
        const float* Xs = (const float*)(smem + X_STAGE);
        for (int t = 0; t < T_DIM; ++t) {
            float dr[20], xc[2];
            #pragma unroll
            for (int mt = 0; mt < 10; ++mt) {
                dr[mt * 2]     = Ds[t * KDIM + mt * 16 + g];
                dr[mt * 2 + 1] = Ds[t * KDIM + mt * 16 + g + 8];
            }
            xc[0] = Xs[t * PCOLS + wid * 8 + i4 * 2];
            xc[1] = Xs[t * PCOLS + wid * 8 + i4 * 2 + 1];
            #pragma unroll
            for (int mt = 0; mt < 10; ++mt)
                #pragma unroll
                for (int q = 0; q < 4; ++q)
                    dty[mt * 4 + q] =
                        fmaf(dr[mt * 2 + (q >> 1)], xc[q & 1], dty[mt * 4 + q]);
        }
        __syncthreads();   // staging consumed (YBUF region reused below)
        #pragma unroll
        for (int mt = 0; mt < 10; ++mt) {
            int f = wid * 10 + mt;
            *(float4*)(smem + DTY_OFF + (f * 32 + l) * 16) =
                make_float4(dty[mt * 4 + 0] * linv, dty[mt * 4 + 1] * linv,
                            dty[mt * 4 + 2] * linv, dty[mt * 4 + 3] * linv);
        }
    }

    // ---- pack stage-1 operand: D48[48,160], k-PERMUTED (v0=row j, v1=row j+8)
    for (int e = tid; e < 30 * 32 * 4; e += NTHREADS) {
        int frag = e >> 7;
        int lane = (e >> 2) & 31;
        int reg  = e & 3;
        int mt   = frag / 10, ks = frag % 10;
        int r  = mt * 16 + (lane >> 2) + ((reg & 1) ? 8 : 0);
        int k0 = ks * 16 + (lane & 3) + ((reg & 2) ? 4 : 0);
        float v0 = (r < T_DIM) ? g_Dmat[r * KDIM + k0] : 0.0f;
        float v1 = (r < T_DIM) ? g_Dmat[r * KDIM + k0 + 8] : 0.0f;
        uint32_t hi, lo;
        split_pack(v0, v1, hi, lo);
        *(uint32_t*)(smem + A1H_OFF + e * 4) = hi;
        *(uint32_t*)(smem + A1L_OFF + e * 4) = lo;
    }
    // ---- pack stage-2 operand: (-linv)*D^T [160,48], k-PERMUTED ----
    for (int e = tid; e < 30 * 32 * 4; e += NTHREADS) {
        int frag = e >> 7;
        int lane = (e >> 2) & 31;
        int reg  = e & 3;
        int mt   = frag / 3, ks = frag % 3;
        int r  = mt * 16 + (lane >> 2) + ((reg & 1) ? 8 : 0);
        int k0 = ks * 16 + (lane & 3) + ((reg & 2) ? 4 : 0);
        float v0 = (k0 < T_DIM) ? -linv * g_Dmat[k0 * KDIM + r] : 0.0f;
        float v1 = (k0 + 8 < T_DIM) ? -linv * g_Dmat[(k0 + 8) * KDIM + r] : 0.0f;
        uint32_t hi, lo;
        split_pack(v0, v1, hi, lo);
        *(uint32_t*)(smem + A2H_OFF + e * 4) = hi;
        *(uint32_t*)(smem + A2L_OFF + e * 4) = lo;
    }
    // ---- zero packed y/z buffers ----
    for (int e = tid; e < (YBUF_WARP * 8 + ZBUF_WARP * 8) / 16; e += NTHREADS)
        ((uint4*)(smem + YBUF_OFF))[e] = make_uint4(0, 0, 0, 0);

    float xold[40], yreg[40];
    #pragma unroll
    for (int v = 0; v < 40; ++v) { xold[v] = 0.0f; yreg[v] = 0.0f; }
    __syncthreads();   // all packing done before any warp starts iterating

    char* yb = smem + YBUF_OFF + wid * YBUF_WARP;
    char* zb = smem + ZBUF_OFF + wid * ZBUF_WARP;

    // ---- main loop: warp-autonomous ----
    int it = 0;
    for (; it < MAXIT; ++it) {
        // ===== stage 1: z = D48 @ y =====
        float z1[3][4];
        #pragma unroll
        for (int m = 0; m < 3; ++m)
            #pragma unroll
            for (int q = 0; q < 4; ++q) z1[m][q] = 0.0f;

        #pragma unroll 2
        for (int ks = 0; ks < 10; ++ks) {
            uint2 u0 = *(const uint2*)(yb + (((ks * 8 + i4)     ) * PSTR + g) * 8);
            uint2 u1 = *(const uint2*)(yb + (((ks * 8 + i4 + 4) ) * PSTR + g) * 8);
            uint32_t bh[2] = {u0.x, u1.x};
            uint32_t bl[2] = {u0.y, u1.y};
            uint32_t ah[3][4], al[3][4];
            #pragma unroll
            for (int mt = 0; mt < 3; ++mt) {
                int fi = (mt * 10 + ks) * 32 + l;
                uint4 Ah = *(const uint4*)(smem + A1H_OFF + fi * 16);
                uint4 Al = *(const uint4*)(smem + A1L_OFF + fi * 16);
                ah[mt][0] = Ah.x; ah[mt][1] = Ah.y; ah[mt][2] = Ah.z; ah[mt][3] = Ah.w;
                al[mt][0] = Al.x; al[mt][1] = Al.y; al[mt][2] = Al.z; al[mt][3] = Al.w;
            }
            #pragma unroll
            for (int mt = 0; mt < 3; ++mt) mma_bf16(z1[mt], ah[mt], bh);
            #pragma unroll
            for (int mt = 0; mt < 3; ++mt) mma_bf16(z1[mt], ah[mt], bl);
            #pragma unroll
            for (int mt = 0; mt < 3; ++mt) mma_bf16(z1[mt], al[mt], bh);
        }
        // pack z pairs: P = mt*8 + g, cols i4*2, i4*2+1
        #pragma unroll
        for (int mt = 0; mt < 3; ++mt) {
            uint32_t h0, l0, h1, l1;
            split_pack(z1[mt][0], z1[mt][2], h0, l0);
            split_pack(z1[mt][1], z1[mt][3], h1, l1);
            *(uint4*)(zb + ((mt * 8 + g) * PSTR + i4 * 2) * 8) =
                make_uint4(h0, l0, h1, l1);
        }
        __syncwarp();

        // ===== stage 2: acc = DtY + (-linv*D^T) @ z =====
        float acc[10][4];
        #pragma unroll
        for (int mt = 0; mt < 10; ++mt) {
            float4 c = *(const float4*)(smem + DTY_OFF + ((wid * 10 + mt) * 32 + l) * 16);
            acc[mt][0] = c.x; acc[mt][1] = c.y; acc[mt][2] = c.z; acc[mt][3] = c.w;
        }
        #pragma unroll
        for (int ks = 0; ks < 3; ++ks) {
            uint2 u0 = *(const uint2*)(zb + ((ks * 8 + i4)     * PSTR + g) * 8);
            uint2 u1 = *(const uint2*)(zb + ((ks * 8 + i4 + 4) * PSTR + g) * 8);
            uint32_t bh[2] = {u0.x, u1.x};
            uint32_t bl[2] = {u0.y, u1.y};
            #pragma unroll
            for (int half = 0; half < 2; ++half) {
                uint32_t ah[5][4], al[5][4];
                #pragma unroll
                for (int m5 = 0; m5 < 5; ++m5) {
                    int mt = half * 5 + m5;
                    int fi = (mt * 3 + ks) * 32 + l;
                    uint4 Ah = *(const uint4*)(smem + A2H_OFF + fi * 16);
                    uint4 Al = *(const uint4*)(smem + A2L_OFF + fi * 16);
                    ah[m5][0] = Ah.x; ah[m5][1] = Ah.y; ah[m5][2] = Ah.z; ah[m5][3] = Ah.w;
                    al[m5][0] = Al.x; al[m5][1] = Al.y; al[m5][2] = Al.z; al[m5][3] = Al.w;
                }
                #pragma unroll
                for (int m5 = 0; m5 < 5; ++m5) mma_bf16(acc[half * 5 + m5], ah[m5], bh);
                #pragma unroll
                for (int m5 = 0; m5 < 5; ++m5) mma_bf16(acc[half * 5 + m5], ah[m5], bl);
                #pragma unroll
                for (int m5 = 0; m5 < 5; ++m5) mma_bf16(acc[half * 5 + m5], al[m5], bh);
            }
        }

        // ===== epilogue (speculative): shrink + momentum + pack y =====
        const float tt = tts_s[it];
        float dsum = 0.0f;
        #pragma unroll
        for (int mt = 0; mt < 10; ++mt) {
            float yn[4];
            #pragma unroll
            for (int q = 0; q < 4; ++q) {
                int ix = mt * 4 + q;
                float v  = acc[mt][q] + yreg[ix];
                float a  = fabsf(v) - lambd;
                float xn = (a > 0.0f) ? copysignf(a, v) : 0.0f;
                float xo = xold[ix];
                float d  = xn - xo;
                dsum = fmaf(d, d, dsum);
                yn[q] = fmaf(tt, d, xn);
                xold[ix] = xn;
                yreg[ix] = yn[q];
            }
            uint32_t h0, l0, h1, l1;
            split_pack(yn[0], yn[2], h0, l0);
            split_pack(yn[1], yn[3], h1, l1);
            *(uint4*)(yb + ((mt * 8 + g) * PSTR + i4 * 2) * 8) =
                make_uint4(h0, l0, h1, l1);
        }
        __syncwarp();

        // ===== publish partial =====
        float ws = warp_sum(dsum);
        if (l == 0) {
            red2[(it & 3) * 8 + wid] = ws;
            __threadfence_block();
            atomicAdd(&wcnt[it & 3], 1);
        }

        // ===== warp0 = agent: aggregate iteration it =====
        if (wid == 0) {
            if (l == 0) {
                while (*((volatile int*)&wcnt[it & 3]) < 8) { __nanosleep(32); }
                __threadfence_block();
                float s = 0.0f;
                #pragma unroll
                for (int i = 0; i < 8; ++i) s += red2[(it & 3) * 8 + i];
                wcnt[it & 3] = 0;
                g_part[(it & 3) * NCTA + cta] = s;
                __threadfence();
                unsigned tk = atomicAdd(&g_count, 1);
                if (tk == (unsigned)(NCTA - 1)) {
                    g_count = 0;
                    __threadfence();
                    atomicAdd(&g_gen, 1);
                }
            }
            __syncwarp();
        }

        // ===== decision for J = it-1 =====
        int stop = 0;
        if (it > 0) {
            const int J = it - 1;
            if (wid == 0) {
                if (l == 0) {
                    while (*((volatile unsigned*)&g_gen) < (unsigned)it) { __nanosleep(32); }
                }
                __syncwarp();
                float s = *((volatile float*)(g_part + (J & 3) * NCTA + l));
                s += *((volatile float*)(g_part + (J & 3) * NCTA + l + 32));
                s += *((volatile float*)(g_part + (J & 3) * NCTA + l + 64));
                s += *((volatile float*)(g_part + (J & 3) * NCTA + l + 96));
                float tot = warp_sum(s);
                if (l == 0) {
                    float denom = (J == 0) ? (float)PDIM : (float)KDIM;
                    decv[J & 3] = (sqrtf(tot) < TOL_C * denom) ? 1 : 0;
                    __threadfence_block();
                    *((volatile int*)&deci[J & 3]) = J;
                }
                __syncwarp();
                stop = decv[J & 3];
            } else {
                if (l == 0) {
                    while (*((volatile int*)&deci[J & 3]) != J) { __nanosleep(32); }
                }
                __syncwarp();
                __threadfence_block();
                stop = decv[J & 3];
            }
            if (stop) {
                // rollback speculative epilogue it: x_it = xn - (yn - xn)/tt
                float inv_tt = 1.0f / tt;
                #pragma unroll
                for (int v = 0; v < 40; ++v)
                    xold[v] = xold[v] - (yreg[v] - xold[v]) * inv_tt;
                break;
            }
        }
    }

    // ---- output: out[(b*160 + row)*4096 + p0 + col] ----
    #pragma unroll
    for (int mt = 0; mt < 10; ++mt)
        #pragma unroll
        for (int q = 0; q < 4; ++q) {
            int row = mt * 16 + g + ((q >> 1) << 3);
            int col = wid * 8 + i4 * 2 + (q & 1);
            out[((size_t)b * KDIM + row) * PDIM + p0 + col] = xold[mt * 4 + q];
        }
}

// ---------------- launch ----------------
extern "C" void kernel_launch(void* const* d_in, const int* in_sizes, int n_in,
                              void* d_out, int out_size) {
    const float* Drr    = (const float*)d_in[0];
    const float* Dtheta = (const float*)d_in[1];
    const float* x      = (const float*)d_in[2];
    float* out = (float*)d_out;

    cudaFuncSetAttribute(fista_kernel, cudaFuncAttributeMaxDynamicSharedMemorySize, SMEM_TOTAL);
    setup_kernel<<<1, 1024>>>(Drr, Dtheta);
    fista_kernel<<<NCTA, NTHREADS, SMEM_TOTAL>>>(x, out);
}

// round 15
// speedup vs baseline: 1.4489x; 1.4489x over previous
#include <cuda_runtime.h>
#include <cuda_bf16.h>
#include <math.h>
#include <stdint.h>

// Problem constants
#define T_DIM   36
#define NPOLES  40
#define KDIM    160
#define PDIM    4096
#define PCOLS   64           // p columns per CTA
#define NCTA    128
#define NTHREADS 256         // 8 warps
#define MAXIT   100
#define LAM_C   0.1f
#define TOL_C   1e-4f

// LDS.64 pairbank = (S/2 mod 16)*g + i4 = 4g + i4 -> exactly 2 lanes/bank (optimal)
#define YSTR    168          // y fp32 column stride (words)
#define ZSTR    72           // z fp32 column stride (words)

// ---- dynamic smem layout (bytes) ----
#define RED_OFF   0          // 8 floats (per-warp partials)
#define STOP_OFF  64
#define TTS_OFF   128        // 100 floats
#define A1H_OFF   1024                  // D48 frags: 30*512 = 15360
#define A1L_OFF   (A1H_OFF + 15360)
#define A2H_OFF   (A1L_OFF + 15360)     // -linv*D^T frags
#define A2L_OFF   (A2H_OFF + 15360)
#define DTY_OFF   (A2L_OFF + 15360)     // 80 c-frags * 512 = 40960
#define Y_OFF     (DTY_OFF + 40960)     // 64 * 168 * 4 = 43008
#define Z_OFF     (Y_OFF + 43008)       // 64 * 72 * 4 = 18432
#define SMEM_TOTAL (Z_OFF + 18432)      // 164864
// startup staging (inside Y region, consumed before y zeroing):
#define DICT_STAGE Y_OFF                // dict [36][160] fp32 = 23040
#define X_STAGE   (Y_OFF + 23040)       // x tile [36][64] fp32 = 9216

// ---------------- device globals ----------------
__device__ float    g_Dmat[T_DIM * KDIM];   // [t][k] normalized dictionary
__device__ float    g_lambd;
__device__ float    g_linv;
__device__ float    g_tts[MAXIT];
__device__ float    g_part[NCTA];
__device__ unsigned g_count;
__device__ unsigned g_gen;                  // monotonic: # completed iterations

// ---------------- helpers ----------------
__device__ __forceinline__ void mma_bf16(float* c, const uint32_t* a, const uint32_t* b) {
    asm volatile(
        "mma.sync.aligned.m16n8k16.row.col.f32.bf16.bf16.f32 "
        "{%0,%1,%2,%3}, {%4,%5,%6,%7}, {%8,%9}, {%0,%1,%2,%3};"
        : "+f"(c[0]), "+f"(c[1]), "+f"(c[2]), "+f"(c[3])
        : "r"(a[0]), "r"(a[1]), "r"(a[2]), "r"(a[3]), "r"(b[0]), "r"(b[1]));
}
__device__ __forceinline__ void split_pack(float v0, float v1, uint32_t& hi, uint32_t& lo) {
    asm("cvt.rn.bf16x2.f32 %0, %1, %2;" : "=r"(hi) : "f"(v1), "f"(v0));
    float h0 = __uint_as_float(hi << 16);
    float h1 = __uint_as_float(hi & 0xffff0000u);
    asm("cvt.rn.bf16x2.f32 %0, %1, %2;" : "=r"(lo) : "f"(v1 - h1), "f"(v0 - h0));
}
__device__ __forceinline__ float warp_sum(float v) {
    v += __shfl_xor_sync(0xFFFFFFFFu, v, 16);
    v += __shfl_xor_sync(0xFFFFFFFFu, v, 8);
    v += __shfl_xor_sync(0xFFFFFFFFu, v, 4);
    v += __shfl_xor_sync(0xFFFFFFFFu, v, 2);
    v += __shfl_xor_sync(0xFFFFFFFFu, v, 1);
    return v;
}

// ---------------- setup (1024 threads; no explicit A matrix) ----------------
__global__ void setup_kernel(const float* __restrict__ Drr,
                             const float* __restrict__ Dtheta) {
    __shared__ float rbuf[32];
    const int tid = threadIdx.x;

    if (tid < KDIM) {
        const int j = tid;
        const int g = j / NPOLES;
        const int n = j % NPOLES;
        const float rr = Drr[n];
        const float th = Dtheta[n];
        float vals[T_DIM];
        float pr = 1.0f, n2 = 0.0f;
        for (int i = 0; i < T_DIM; ++i) {
            float ang  = (float)i * th;
            float base = (g < 2) ? cosf(ang) : sinf(ang);
            float v = pr * base;
            if ((g & 1) && (i & 1)) v = -v;
            vals[i] = v; n2 += v * v; pr *= rr;
        }
        float G  = (n2 == 0.0f) ? 6.0f : sqrtf(n2);
        float gi = 1.0f / G;
        for (int i = 0; i < T_DIM; ++i) g_Dmat[i * KDIM + j] = vals[i] * gi;
    }
    __syncthreads();

    float sq = 0.0f;
    for (int e = tid; e < KDIM * KDIM; e += 1024) {
        int i = e / KDIM, jj = e % KDIM;
        float s = 0.0f;
        for (int t = 0; t < T_DIM; ++t)
            s += g_Dmat[t * KDIM + i] * g_Dmat[t * KDIM + jj];
        sq += s * s;
    }
    float ws = warp_sum(sq);
    if ((tid & 31) == 0) rbuf[tid >> 5] = ws;
    __syncthreads();
    if (tid == 0) {
        float tot = 0.0f;
        for (int i = 0; i < 32; ++i) tot += rbuf[i];
        float L = sqrtf(tot);
        float linv = 1.0f / L;
        g_linv  = linv;
        g_lambd = LAM_C * linv;
        double t = 1.0;
        for (int k = 0; k < MAXIT; ++k) {
            double tn = (1.0 + sqrt(1.0 + 4.0 * t * t)) * 0.5;
            g_tts[k] = (float)((t - 1.0) / tn);
            t = tn;
        }
        g_count = 0;
        g_gen   = 0;
    }
    if (tid < NCTA) g_part[tid] = 0.0f;
}

// ---------------- persistent FISTA kernel (factorized, 8 warps) ------------
// stage1: warp w: z[48, cols w*8..w*8+8) = D48 @ y, full ks.
// stage2: warp (wm, wn): acc = DtY - linv*D^T @ z, 16-col stripes, 80-row halves.
// epilogue: v = acc + y_reg ; shrink ; momentum.
__global__ void __launch_bounds__(NTHREADS, 1)
fista_kernel(const float* __restrict__ x_in, float* __restrict__ out) {
    extern __shared__ __align__(16) char smem[];
    float* red    = (float*)(smem + RED_OFF);
    int*   s_stop = (int*)(smem + STOP_OFF);
    float* tts_s  = (float*)(smem + TTS_OFF);

    const int tid = threadIdx.x;
    const int wid = tid >> 5;
    const int l   = tid & 31;
    const int wm  = wid >> 2;          // stage2: 0..1 (80-row half)
    const int wn  = wid & 3;           // stage2: 0..3 (16-col stripe)
    const int g   = l >> 2;
    const int i4  = l & 3;
    const int cta = blockIdx.x;
    const int b   = cta >> 6;
    const int p0  = (cta & 63) * PCOLS;

    const float linv  = g_linv;
    const float lambd = g_lambd;

    // ---- stage dict and x tile fp32; copy tts ----
    for (int e = tid; e < T_DIM * KDIM; e += NTHREADS)
        *(float*)(smem + DICT_STAGE + e * 4) = g_Dmat[e];
    for (int e = tid; e < T_DIM * PCOLS; e += NTHREADS) {
        int t = e >> 6, pp = e & 63;
        *(float*)(smem + X_STAGE + e * 4) = x_in[(b * T_DIM + t) * PDIM + p0 + pp];
    }
    if (tid < MAXIT) tts_s[tid] = g_tts[tid];
    __syncthreads();

    // ---- DtY = linv * D^T x -> regs (c-frag order, stage2 mapping) ----
    {
        float dty[40];
        #pragma unroll
        for (int v = 0; v < 40; ++v) dty[v] = 0.0f;
        const float* Ds = (const float*)(smem + DICT_STAGE);
        const float* Xs = (const float*)(smem + X_STAGE);
        for (int t = 0; t < T_DIM; ++t) {
            float dr[10], xc[4];
            #pragma unroll
            for (int mt = 0; mt < 5; ++mt) {
                dr[mt * 2]     = Ds[t * KDIM + wm * 80 + mt * 16 + g];
                dr[mt * 2 + 1] = Ds[t * KDIM + wm * 80 + mt * 16 + g + 8];
            }
            #pragma unroll
            for (int nt = 0; nt < 2; ++nt) {
                xc[nt * 2]     = Xs[t * PCOLS + wn * 16 + nt * 8 + i4 * 2];
                xc[nt * 2 + 1] = Xs[t * PCOLS + wn * 16 + nt * 8 + i4 * 2 + 1];
            }
            #pragma unroll
            for (int mt = 0; mt < 5; ++mt)
                #pragma unroll
                for (int nt = 0; nt < 2; ++nt)
                    #pragma unroll
                    for (int q = 0; q < 4; ++q)
                        dty[(mt * 2 + nt) * 4 + q] =
                            fmaf(dr[mt * 2 + (q >> 1)], xc[nt * 2 + (q & 1)],
                                 dty[(mt * 2 + nt) * 4 + q]);
        }
        __syncthreads();   // dict/x staging consumed (Y region reused below)

        // store DtY to smem (c-frag layout, 80 frags) — frees registers
        #pragma unroll
        for (int mt = 0; mt < 5; ++mt)
            #pragma unroll
            for (int nt = 0; nt < 2; ++nt) {
                int f = (wm * 5 + mt) * 8 + wn * 2 + nt;
                *(float4*)(smem + DTY_OFF + (f * 32 + l) * 16) =
                    make_float4(dty[(mt * 2 + nt) * 4 + 0] * linv,
                                dty[(mt * 2 + nt) * 4 + 1] * linv,
                                dty[(mt * 2 + nt) * 4 + 2] * linv,
                                dty[(mt * 2 + nt) * 4 + 3] * linv);
            }
    }

    // ---- pack stage-1 operand: D48[48,160] (rows>=36 zero), f1 = mt*10+ks ----
    for (int e = tid; e < 30 * 32 * 4; e += NTHREADS) {
        int frag = e >> 7;
        int lane = (e >> 2) & 31;
        int reg  = e & 3;
        int mt   = frag / 10, ks = frag % 10;
        int r = mt * 16 + (lane >> 2) + ((reg & 1) ? 8 : 0);
        int k = ks * 16 + (lane & 3) * 2 + ((reg & 2) ? 8 : 0);
        float v0 = (r < T_DIM) ? g_Dmat[r * KDIM + k] : 0.0f;
        float v1 = (r < T_DIM) ? g_Dmat[r * KDIM + k + 1] : 0.0f;
        uint32_t hi, lo;
        split_pack(v0, v1, hi, lo);
        *(uint32_t*)(smem + A1H_OFF + e * 4) = hi;
        *(uint32_t*)(smem + A1L_OFF + e * 4) = lo;
    }
    // ---- pack stage-2 operand: (-linv)*D^T [160,48] (cols>=36 zero), f2 = mt*3+ks
    for (int e = tid; e < 30 * 32 * 4; e += NTHREADS) {
        int frag = e >> 7;
        int lane = (e >> 2) & 31;
        int reg  = e & 3;
        int mt   = frag / 3, ks = frag % 3;
        int r = mt * 16 + (lane >> 2) + ((reg & 1) ? 8 : 0);
        int k = ks * 16 + (lane & 3) * 2 + ((reg & 2) ? 8 : 0);
        float v0 = (k < T_DIM) ? -linv * g_Dmat[k * KDIM + r] : 0.0f;
        float v1 = (k + 1 < T_DIM) ? -linv * g_Dmat[(k + 1) * KDIM + r] : 0.0f;
        uint32_t hi, lo;
        split_pack(v0, v1, hi, lo);
        *(uint32_t*)(smem + A2H_OFF + e * 4) = hi;
        *(uint32_t*)(smem + A2L_OFF + e * 4) = lo;
    }
    // ---- zero y (fp32) ----
    for (int e = tid; e < PCOLS * YSTR; e += NTHREADS)
        *(float*)(smem + Y_OFF + e * 4) = 0.0f;

    float xold[40], yreg[40];
    #pragma unroll
    for (int v = 0; v < 40; ++v) { xold[v] = 0.0f; yreg[v] = 0.0f; }
    __syncthreads();

    const float* Yp = (const float*)(smem + Y_OFF);
    const float* Zp = (const float*)(smem + Z_OFF);
    float*       Zw = (float*)(smem + Z_OFF);

    // ---- main FISTA loop ----
    for (int it = 0; it < MAXIT; ++it) {
        // ===== stage 1: z[48, 8 cols of warp] = D48 @ y, full ks =====
        float z1[3][4];
        #pragma unroll
        for (int mt = 0; mt < 3; ++mt)
            #pragma unroll
            for (int q = 0; q < 4; ++q) z1[mt][q] = 0.0f;

        #pragma unroll 2
        for (int ks = 0; ks < 10; ++ks) {
            const float* yrow = Yp + (wid * 8 + g) * YSTR + ks * 16 + i4 * 2;
            float2 v0 = *(const float2*)(yrow);
            float2 v1 = *(const float2*)(yrow + 8);
            uint32_t bh[2], bl[2];
            split_pack(v0.x, v0.y, bh[0], bl[0]);
            split_pack(v1.x, v1.y, bh[1], bl[1]);
            uint32_t a1h[3][4], a1l[3][4];
            #pragma unroll
            for (int mt = 0; mt < 3; ++mt) {
                int fi = (mt * 10 + ks) * 32 + l;
                uint4 Ah = *(const uint4*)(smem + A1H_OFF + fi * 16);
                uint4 Al = *(const uint4*)(smem + A1L_OFF + fi * 16);
                a1h[mt][0] = Ah.x; a1h[mt][1] = Ah.y; a1h[mt][2] = Ah.z; a1h[mt][3] = Ah.w;
                a1l[mt][0] = Al.x; a1l[mt][1] = Al.y; a1l[mt][2] = Al.z; a1l[mt][3] = Al.w;
            }
            #pragma unroll
            for (int mt = 0; mt < 3; ++mt) mma_bf16(z1[mt], a1h[mt], bh);
            #pragma unroll
            for (int mt = 0; mt < 3; ++mt) mma_bf16(z1[mt], a1h[mt], bl);
            #pragma unroll
            for (int mt = 0; mt < 3; ++mt) mma_bf16(z1[mt], a1l[mt], bh);
        }
        // write z (conflict: 2-way stores, off critical path)
        #pragma unroll
        for (int mt = 0; mt < 3; ++mt)
            #pragma unroll
            for (int q = 0; q < 4; ++q) {
                int row = mt * 16 + g + ((q >> 1) << 3);
                int col = wid * 8 + i4 * 2 + (q & 1);
                Zw[col * ZSTR + row] = z1[mt][q];
            }

        // ---- HOISTED (hazard-free) loads: acc init + stage2 ks=0 A-frags ----
        float acc[10][4];
        #pragma unroll
        for (int mt = 0; mt < 5; ++mt)
            #pragma unroll
            for (int nt = 0; nt < 2; ++nt) {
                int f = (wm * 5 + mt) * 8 + wn * 2 + nt;
                float4 c = *(const float4*)(smem + DTY_OFF + (f * 32 + l) * 16);
                acc[mt * 2 + nt][0] = c.x; acc[mt * 2 + nt][1] = c.y;
                acc[mt * 2 + nt][2] = c.z; acc[mt * 2 + nt][3] = c.w;
            }
        uint32_t ah0[5][4], al0[5][4];
        #pragma unroll
        for (int mt = 0; mt < 5; ++mt) {
            int fi = ((wm * 5 + mt) * 3 + 0) * 32 + l;
            uint4 Ah = *(const uint4*)(smem + A2H_OFF + fi * 16);
            uint4 Al = *(const uint4*)(smem + A2L_OFF + fi * 16);
            ah0[mt][0] = Ah.x; ah0[mt][1] = Ah.y; ah0[mt][2] = Ah.z; ah0[mt][3] = Ah.w;
            al0[mt][0] = Al.x; al0[mt][1] = Al.y; al0[mt][2] = Al.z; al0[mt][3] = Al.w;
        }

        // join the gen-poll (partials of it-1 globally visible after this)
        if (it > 0 && tid == 0) {
            while (*((volatile unsigned*)&g_gen) < (unsigned)it) { __nanosleep(32); }
        }
        __syncthreads();   // sync_Z: z written; y reads done; poll joined

        // stop decision for it-1, overlapped with stage 2 (w0 only)
        if (it > 0 && wid == 0) {
            float s = *((volatile float*)(g_part + l));
            s += *((volatile float*)(g_part + l + 32));
            s += *((volatile float*)(g_part + l + 64));
            s += *((volatile float*)(g_part + l + 96));
            float tot = warp_sum(s);
            if (l == 0) {
                float denom = (it == 1) ? (float)PDIM : (float)KDIM;
                *s_stop = (sqrtf(tot) < TOL_C * denom) ? 1 : 0;
            }
        }

        // ===== stage 2: acc += (-linv*D^T) @ z =====
        #pragma unroll
        for (int ks = 0; ks < 3; ++ks) {
            uint32_t bh[2][2], bl[2][2];
            #pragma unroll
            for (int nt = 0; nt < 2; ++nt) {
                const int zoff = (wn * 16 + nt * 8 + g) * ZSTR + ks * 16 + i4 * 2;
                float2 a0 = *(const float2*)(Zp + zoff);
                float2 a1 = *(const float2*)(Zp + zoff + 8);
                split_pack(a0.x, a0.y, bh[nt][0], bl[nt][0]);
                split_pack(a1.x, a1.y, bh[nt][1], bl[nt][1]);
            }
            uint32_t ah[5][4], al[5][4];
            if (ks == 0) {
                #pragma unroll
                for (int mt = 0; mt < 5; ++mt)
                    #pragma unroll
                    for (int r = 0; r < 4; ++r) { ah[mt][r] = ah0[mt][r]; al[mt][r] = al0[mt][r]; }
            } else {
                #pragma unroll
                for (int mt = 0; mt < 5; ++mt) {
                    int fi = ((wm * 5 + mt) * 3 + ks) * 32 + l;
                    uint4 Ah = *(const uint4*)(smem + A2H_OFF + fi * 16);
                    uint4 Al = *(const uint4*)(smem + A2L_OFF + fi * 16);
                    ah[mt][0] = Ah.x; ah[mt][1] = Ah.y; ah[mt][2] = Ah.z; ah[mt][3] = Ah.w;
                    al[mt][0] = Al.x; al[mt][1] = Al.y; al[mt][2] = Al.z; al[mt][3] = Al.w;
                }
            }
            #pragma unroll
            for (int mt = 0; mt < 5; ++mt)
                #pragma unroll
                for (int nt = 0; nt < 2; ++nt)
                    mma_bf16(acc[mt * 2 + nt], ah[mt], bh[nt]);
            #pragma unroll
            for (int mt = 0; mt < 5; ++mt)
                #pragma unroll
                for (int nt = 0; nt < 2; ++nt)
                    mma_bf16(acc[mt * 2 + nt], ah[mt], bl[nt]);
            #pragma unroll
            for (int mt = 0; mt < 5; ++mt)
                #pragma unroll
                for (int nt = 0; nt < 2; ++nt)
                    mma_bf16(acc[mt * 2 + nt], al[mt], bh[nt]);
        }

        const float tt = tts_s[it];
        float dsum = 0.0f;

        // epilogue (speculative): v = acc + y_reg ; shrink ; momentum
        #pragma unroll
        for (int mt = 0; mt < 5; ++mt)
            #pragma unroll
            for (int nt = 0; nt < 2; ++nt)
                #pragma unroll
                for (int q = 0; q < 4; ++q) {
                    int ix  = (mt * 2 + nt) * 4 + q;
                    float v  = acc[mt * 2 + nt][q] + yreg[ix];
                    float a  = fabsf(v) - lambd;
                    float xn = (a > 0.0f) ? copysignf(a, v) : 0.0f;
                    float xo = xold[ix];
                    float d  = xn - xo;
                    dsum = fmaf(d, d, dsum);
                    float yn = fmaf(tt, d, xn);
                    xold[ix] = xn;
                    yreg[ix] = yn;
                    int row = wm * 80 + mt * 16 + g + ((q >> 1) << 3);
                    int col = wn * 16 + nt * 8 + i4 * 2 + (q & 1);
                    *(float*)(smem + Y_OFF + (col * YSTR + row) * 4) = yn;
                }

        float ws = warp_sum(dsum);
        if (l == 0) red[wid] = ws;
        __syncthreads();   // sync_B: y + red + s_stop visible

        if (it > 0 && *s_stop) {
            // rollback speculative epilogue: xo = xn - (y - xn)/tt  (tt>0 for it>=1)
            float inv_tt = 1.0f / tt;
            #pragma unroll
            for (int v = 0; v < 40; ++v)
                xold[v] = xold[v] - (yreg[v] - xold[v]) * inv_tt;
            break;
        }

        // publish partial + arrive (no wait; decision deferred)
        if (tid == 0) {
            float s = red[0];
            #pragma unroll
            for (int i = 1; i < 8; ++i) s += red[i];
            g_part[cta] = s;
            __threadfence();
            unsigned tk = atomicAdd(&g_count, 1);
            if (tk == (unsigned)(NCTA - 1)) {
                g_count = 0;
                __threadfence();
                atomicAdd(&g_gen, 1);
            }
        }
    }

    // ---- output: out[(b*160 + row)*4096 + p0 + col] ----
    #pragma unroll
    for (int mt = 0; mt < 5; ++mt)
        #pragma unroll
        for (int nt = 0; nt < 2; ++nt)
            #pragma unroll
            for (int q = 0; q < 4; ++q) {
                int row = wm * 80 + mt * 16 + g + ((q >> 1) << 3);
                int col = wn * 16 + nt * 8 + i4 * 2 + (q & 1);
                out[((size_t)b * KDIM + row) * PDIM + p0 + col] =
                    xold[(mt * 2 + nt) * 4 + q];
            }
}

// ---------------- launch ----------------
extern "C" void kernel_launch(void* const* d_in, const int* in_sizes, int n_in,
                              void* d_out, int out_size) {
    const float* Drr    = (const float*)d_in[0];
    const float* Dtheta = (const float*)d_in[1];
    const float* x      = (const float*)d_in[2];
    float* out = (float*)d_out;

    cudaFuncSetAttribute(fista_kernel, cudaFuncAttributeMaxDynamicSharedMemorySize, SMEM_TOTAL);
    setup_kernel<<<1, 1024>>>(Drr, Dtheta);
    fista_kernel<<<NCTA, NTHREADS, SMEM_TOTAL>>>(x, out);
}